// round 13
// baseline (speedup 1.0000x reference)
#include <cuda_runtime.h>
#include <cstdint>

// TropicalLinear forward on GB300:
//   out[n,o] = max_i( x[n,i] + w[o,i] ) + bias[o]
//
// R12 == R11 (previous round was an infra failure, never executed):
//   intra-warp k-split (max is associative): each lane accumulates a
//   disjoint k-slice, butterfly shfl-max at the end.
//   - NO split-K scratch, NO grid barrier, NO combine: one straight kernel.
//   - natural row-major smem (no transpose, no padding): lanes read
//     consecutive float4s of a row -> bank-clean by construction.
//   - k-pair packed add.rn.f32x2 on natural adjacent k's.
//   - 1024 CTAs x 256 thr, warp tile 2n x 8o, CTA tile 8n x 16o,
//     12 KB static smem, __launch_bounds__(256,4) -> 4 CTAs/SM, 32 warps/SM.

#define N_ROWS  128
#define IN_DIM  1024
#define OUT_DIM 1024
#define KC      128                 // k per smem stage
#define NSTAGE  (IN_DIM / KC)       // 8
#define TN      8                   // CTA n-tile
#define TO      16                  // CTA o-tile

__device__ __forceinline__ float neg_inf() { return __int_as_float(0xff800000); }

__device__ __forceinline__ unsigned long long add2(unsigned long long a,
                                                   unsigned long long b) {
    unsigned long long r;
    asm("add.rn.f32x2 %0, %1, %2;" : "=l"(r) : "l"(a), "l"(b));
    return r;
}
__device__ __forceinline__ float lo32(unsigned long long v) {
    return __uint_as_float((unsigned int)v);
}
__device__ __forceinline__ float hi32(unsigned long long v) {
    return __uint_as_float((unsigned int)(v >> 32));
}

extern "C" __global__ void __launch_bounds__(256, 4)
tropical_kernel(const float* __restrict__ x,
                const float* __restrict__ w,
                const float* __restrict__ bias,
                float* __restrict__ out)
{
    // natural row-major tiles, float4 granular: 4 KB + 8 KB = 12 KB static
    __shared__ float4 xs4[TN * (KC / 4)];   // [8 rows][32 float4]
    __shared__ float4 ws4[TO * (KC / 4)];   // [16 rows][32 float4]

    const int tid  = threadIdx.x;
    const int lane = tid & 31;
    const int wid  = tid >> 5;          // 0..7
    const int wn   = wid >> 1;          // 0..3 -> n rows {2wn, 2wn+1}
    const int wo   = wid & 1;           // 0..1 -> o rows {8wo .. 8wo+7}

    const int o0 = blockIdx.x * TO;     // 64 o-tiles
    const int n0 = blockIdx.y * TN;     // 16 n-tiles

    // staging coordinates (row-coalesced: one 512B row-chunk per warp)
    const int srow = tid >> 5;          // 0..7
    const int sc   = tid & 31;          // float4 within row

    float acc[2][8];
#pragma unroll
    for (int i = 0; i < 2; ++i)
#pragma unroll
        for (int j = 0; j < 8; ++j)
            acc[i][j] = neg_inf();

#pragma unroll 1
    for (int s = 0; s < NSTAGE; ++s) {
        const int k0 = s * KC;

        // ---- stage (coalesced LDG.128 -> linear STS.128, conflict-free) ----
        xs4[srow * 32 + sc] =
            *(const float4*)(x + (size_t)(n0 + srow) * IN_DIM + k0 + sc * 4);
#pragma unroll
        for (int it = 0; it < 2; ++it) {
            const int r = srow + it * 8;
            ws4[r * 32 + sc] =
                *(const float4*)(w + (size_t)(o0 + r) * IN_DIM + k0 + sc * 4);
        }
        __syncthreads();

        // ---- compute: lane handles k = k0 + 4*lane .. +3 (disjoint slices) ----
        // all LDS.128 lane-stride 4 floats -> bank-clean
        ulonglong2 xv[2];
#pragma unroll
        for (int i = 0; i < 2; ++i)
            xv[i] = *(const ulonglong2*)&xs4[(2 * wn + i) * 32 + lane];

#pragma unroll
        for (int h = 0; h < 2; ++h) {               // w in halves of 4 o-rows
            ulonglong2 wv[4];
#pragma unroll
            for (int j = 0; j < 4; ++j)
                wv[j] = *(const ulonglong2*)&ws4[(8 * wo + h * 4 + j) * 32 + lane];
#pragma unroll
            for (int i = 0; i < 2; ++i) {
#pragma unroll
                for (int j = 0; j < 4; ++j) {
                    unsigned long long s0 = add2(xv[i].x, wv[j].x);  // k0..k1
                    unsigned long long s1 = add2(xv[i].y, wv[j].y);  // k2..k3
                    float t0 = fmaxf(lo32(s0), hi32(s0));
                    float t1 = fmaxf(lo32(s1), hi32(s1));
                    acc[i][h * 4 + j] = fmaxf(acc[i][h * 4 + j], fmaxf(t0, t1));
                }
            }
        }
        __syncthreads();
    }

    // ---- butterfly shfl-max across lanes (k-slices) ----
#pragma unroll
    for (int i = 0; i < 2; ++i)
#pragma unroll
        for (int j = 0; j < 8; ++j) {
#pragma unroll
            for (int m = 16; m >= 1; m >>= 1)
                acc[i][j] = fmaxf(acc[i][j],
                                  __shfl_xor_sync(0xffffffffu, acc[i][j], m));
        }

    // ---- write: lanes 0..15 each emit one (i,j) output ----
    const int li = lane >> 3;           // 0..1
    const int lj = lane & 7;            // 0..7
    float v = neg_inf();
#pragma unroll
    for (int i = 0; i < 2; ++i)
#pragma unroll
        for (int j = 0; j < 8; ++j)
            if (li == i && lj == j) v = acc[i][j];

    if (lane < 16) {
        const int n = n0 + 2 * wn + li;
        const int o = o0 + 8 * wo + lj;
        out[(size_t)n * OUT_DIM + o] = v + __ldg(&bias[o]);
    }
}

extern "C" void kernel_launch(void* const* d_in, const int* in_sizes, int n_in,
                              void* d_out, int out_size)
{
    const float* x    = (const float*)d_in[0];   // [128, 1024]
    const float* w    = (const float*)d_in[1];   // [1024, 1024]
    const float* bias = (const float*)d_in[2];   // [1024]
    float* out = (float*)d_out;                  // [128, 1024]

    dim3 grid(OUT_DIM / TO, N_ROWS / TN);        // (64, 16) = 1024 CTAs
    tropical_kernel<<<grid, 256>>>(x, w, bias, out);
}